// round 14
// baseline (speedup 1.0000x reference)
#include <cuda_runtime.h>
#include <cuda_fp16.h>

#define NN 100000
#define EE 1250000
#define HH 64
#define NPB 64                        // nodes per gemm-block
#define GBLK ((NN + NPB - 1) / NPB)   // 1563
#define SROW 72                       // smem row stride in halves (ldmatrix conflict-free)
#define NPW 2                         // nodes per gather-warp (wave-quantization fix)
#define GATB ((NN + 8 * NPW - 1) / (8 * NPW))   // 6250 gather blocks

// ---- scratch (device globals, zero-initialized at load; k_offsets re-zeros
// the degree arrays and k_final re-zeros g_total, so every replay sees zeros) ----
__device__ int   g_in_deg[NN];
__device__ int   g_out_deg[NN];
__device__ int   g_total;
__device__ float g_norm_out[NN];
__device__ float g_norm_in[NN];
__device__ int   g_row_off[NN];
__device__ int   g_cursor[NN];        // after k_csrembed: cursor[i] == row end
__device__ int   g_csr[EE];
__device__ __align__(16) float  g_xA[(size_t)NN * HH];    // fp32 node features (ping)
__device__ __align__(16) float  g_xB[(size_t)NN * HH];    // fp32 node features (pong)
__device__ __align__(16) __half g_aggh[(size_t)NN * HH];  // gather out, hi
__device__ __align__(16) __half g_aggl[(size_t)NN * HH];  // gather out, lo
__device__ __align__(16) __half g_Wh[3 * HH * HH];        // W hi, 3 layers
__device__ __align__(16) __half g_Wl[3 * HH * HH];        // W lo, 3 layers

__device__ __forceinline__ void split2(float v, __half& hi, __half& lo) {
    hi = __float2half_rn(v);
    lo = __float2half_rn(v - __half2float(hi));
}

// ---------------- setup kernels ----------------

__global__ void k_degrees(const int* __restrict__ src, const int* __restrict__ dst) {
    int e = blockIdx.x * blockDim.x + threadIdx.x;
    if (e < EE) {
        atomicAdd(&g_out_deg[src[e]], 1);
        atomicAdd(&g_in_deg[dst[e]], 1);
    }
}

// offsets + norms; zeros degree arrays; also splits the 3 weight matrices hi/lo
__global__ void k_offsets(const float* __restrict__ W1, const float* __restrict__ W2,
                          const float* __restrict__ W3) {
    int i = blockIdx.x * blockDim.x + threadIdx.x;
    if (i < NN) {
        int d  = g_in_deg[i];
        int od = g_out_deg[i];
        int off = atomicAdd(&g_total, d);
        g_row_off[i] = off;
        g_cursor[i]  = off;
        g_norm_in[i]  = rsqrtf(fmaxf((float)d, 1.0f));
        g_norm_out[i] = rsqrtf(fmaxf((float)od, 1.0f));
        g_in_deg[i] = 0;
        g_out_deg[i] = 0;
    }
    if (i < 3 * HH * HH) {
        int layer = i >> 12;
        int idx   = i & 4095;
        const float* Wp = (layer == 0) ? W1 : (layer == 1) ? W2 : W3;
        __half hi, lo;
        split2(__ldg(&Wp[idx]), hi, lo);
        g_Wh[i] = hi;
        g_Wl[i] = lo;
    }
}

// CSR scatter fused with fp32 embedding build (xA[n] = norm_out[n]*z_table[z[n]])
__global__ void k_csrembed(const int* __restrict__ src, const int* __restrict__ dst,
                           const int* __restrict__ z, const float* __restrict__ zt) {
    int i = blockIdx.x * blockDim.x + threadIdx.x;
    if (i < EE) {
        int p = atomicAdd(&g_cursor[dst[i]], 1);
        g_csr[p] = src[i];
    }
    if (i < NN * 8) {
        int n  = i >> 3;
        int c8 = (i & 7) << 3;
        float no = g_norm_out[n];
        const float4* r = (const float4*)(zt + (size_t)__ldg(&z[n]) * HH + c8);
        float4 v0 = __ldg(r), v1 = __ldg(r + 1);
        float4* o = (float4*)(g_xA + (size_t)n * HH + c8);
        o[0] = make_float4(v0.x * no, v0.y * no, v0.z * no, v0.w * no);
        o[1] = make_float4(v1.x * no, v1.y * no, v1.z * no, v1.w * no);
    }
}

// ---------------- gather kernel ----------------
// 256 threads, 8 warps, warp = NPW(2) nodes (fine-grained: no wave quantization).
// fp32 feature rows: 2 edges in flight (lanes 0-15 edge A, 16-31 edge B), each
// lane LDG.128s one float4 slice (16 lanes x 16B = 256B row). No converts —
// pure shfl + LDG + FADD. fp32 accumulate, norm_in, hi/lo fp16 split out.

__global__ void __launch_bounds__(256, 8) k_gather(const float* __restrict__ xin)
{
    int t = threadIdx.x;
    int warp = t >> 5;
    int lane = t & 31;
    int half_ = lane >> 4;
    int fl    = lane & 15;
    int gw = blockIdx.x * 8 + warp;   // global warp id

    #pragma unroll 1
    for (int nl = 0; nl < NPW; nl++) {
        int n = gw * NPW + nl;
        if (n >= NN) break;

        int beg = g_row_off[n];
        int end = g_cursor[n];
        float4 acc = make_float4(0.0f, 0.0f, 0.0f, 0.0f);

        for (int base = beg; base < end; base += 32) {
            int cnt = min(32, end - base);
            int idx = (lane < cnt) ? __ldg(&g_csr[base + lane]) : 0;
            #pragma unroll 4
            for (int j = 0; j < cnt; j += 2) {
                int e = j + half_;
                int s = __shfl_sync(0xffffffffu, idx, e);
                if (e < cnt) {
                    float4 v = __ldg((const float4*)(xin + ((size_t)s << 6)) + fl);
                    acc.x += v.x; acc.y += v.y; acc.z += v.z; acc.w += v.w;
                }
            }
        }

        acc.x += __shfl_xor_sync(0xffffffffu, acc.x, 16);
        acc.y += __shfl_xor_sync(0xffffffffu, acc.y, 16);
        acc.z += __shfl_xor_sync(0xffffffffu, acc.z, 16);
        acc.w += __shfl_xor_sync(0xffffffffu, acc.w, 16);

        if (half_ == 0) {
            float ni = g_norm_in[n];
            float vv[4] = {acc.x * ni, acc.y * ni, acc.z * ni, acc.w * ni};
            __half hi[4], lo[4];
            #pragma unroll
            for (int k = 0; k < 4; k++) split2(vv[k], hi[k], lo[k]);
            *(uint2*)(g_aggh + (size_t)n * HH + (fl << 2)) = *(uint2*)hi;
            *(uint2*)(g_aggl + (size_t)n * HH + (fl << 2)) = *(uint2*)lo;
        }
    }
}

// ---------------- mma helpers ----------------

__device__ __forceinline__ unsigned su32(const void* p) {
    return (unsigned)__cvta_generic_to_shared(p);
}
__device__ __forceinline__ void ldmx4(unsigned& r0, unsigned& r1, unsigned& r2,
                                      unsigned& r3, unsigned addr) {
    asm volatile("ldmatrix.sync.aligned.m8n8.x4.shared.b16 {%0,%1,%2,%3}, [%4];"
                 : "=r"(r0), "=r"(r1), "=r"(r2), "=r"(r3) : "r"(addr));
}
__device__ __forceinline__ void ldmx4t(unsigned& r0, unsigned& r1, unsigned& r2,
                                       unsigned& r3, unsigned addr) {
    asm volatile("ldmatrix.sync.aligned.m8n8.x4.trans.shared.b16 {%0,%1,%2,%3}, [%4];"
                 : "=r"(r0), "=r"(r1), "=r"(r2), "=r"(r3) : "r"(addr));
}
__device__ __forceinline__ void mma16816(float* c, unsigned a0, unsigned a1,
                                         unsigned a2, unsigned a3,
                                         unsigned b0, unsigned b1) {
    asm volatile(
        "mma.sync.aligned.m16n8k16.row.col.f32.f16.f16.f32 "
        "{%0,%1,%2,%3}, {%4,%5,%6,%7}, {%8,%9}, {%0,%1,%2,%3};"
        : "+f"(c[0]), "+f"(c[1]), "+f"(c[2]), "+f"(c[3])
        : "r"(a0), "r"(a1), "r"(a2), "r"(a3), "r"(b0), "r"(b1));
}

// ---------------- GEMM kernel (tensor cores, double-fp16, copy staging) ----------------
// 256 threads, 64 nodes/block, static smem 37KB, 4 blocks/SM.
// Staging = pure uint4 copies (hi/lo precomputed). D = Ah*Wh + Ah*Wl + Al*Wh.
// warp w (0..7): m-tile (w&3) x n-half (w>>2). fp32 feature output.

template <bool RELU, bool SCALE_OUT>
__global__ void __launch_bounds__(256, 4) k_gemm(
    const __half* __restrict__ Wh, const __half* __restrict__ Wl,
    const float* __restrict__ b,
    float* __restrict__ xout)
{
    __shared__ __half sW_hi[HH * SROW];
    __shared__ __half sW_lo[HH * SROW];
    __shared__ __half sa_hi[NPB * SROW];
    __shared__ __half sa_lo[NPB * SROW];
    __shared__ float  sb[HH];

    int t = threadIdx.x;

    // W stage: 512 uint4 chunks each (pure copies)
    #pragma unroll
    for (int c = 0; c < 2; c++) {
        int idx = t + c * 256;               // 0..511
        int row = idx >> 3, c8 = (idx & 7) << 3;
        *(uint4*)(sW_hi + row * SROW + c8) = __ldg((const uint4*)Wh + idx);
        *(uint4*)(sW_lo + row * SROW + c8) = __ldg((const uint4*)Wl + idx);
    }
    // agg stage: 512 uint4 chunks each
    #pragma unroll
    for (int c = 0; c < 2; c++) {
        int idx = t + c * 256;
        int row = idx >> 3, c8 = (idx & 7) << 3;
        int node = blockIdx.x * NPB + row;
        uint4 vh = make_uint4(0, 0, 0, 0), vl = make_uint4(0, 0, 0, 0);
        if (node < NN) {
            vh = __ldg((const uint4*)(g_aggh + (size_t)node * HH + c8));
            vl = __ldg((const uint4*)(g_aggl + (size_t)node * HH + c8));
        }
        *(uint4*)(sa_hi + row * SROW + c8) = vh;
        *(uint4*)(sa_lo + row * SROW + c8) = vl;
    }
    if (t < HH) sb[t] = b[t];
    __syncthreads();

    int warp = t >> 5;
    int lane = t & 31;
    int mt = warp & 3;           // m-tile: rows mt*16..+15
    int n0 = (warp >> 2) << 5;   // n-half: cols n0..n0+31

    float c[4][4];
    #pragma unroll
    for (int j = 0; j < 4; j++) {
        int col = n0 + 8 * j + ((lane & 3) << 1);
        float b0v = sb[col], b1v = sb[col + 1];
        c[j][0] = b0v; c[j][1] = b1v; c[j][2] = b0v; c[j][3] = b1v;
    }

    int rIn = (lane & 7) + ((lane >> 3) & 1) * 8;
    int cIn = (lane >> 4) * 8;
    unsigned aoff = ((mt * 16 + rIn) * SROW + cIn) * 2;
    unsigned boff = (rIn * SROW + n0 + cIn) * 2;
    unsigned ah_base = su32(sa_hi) + aoff;
    unsigned al_base = su32(sa_lo) + aoff;
    unsigned bh_base = su32(sW_hi) + boff;
    unsigned bl_base = su32(sW_lo) + boff;

    #pragma unroll
    for (int kt = 0; kt < 4; kt++) {
        unsigned ah0, ah1, ah2, ah3, al0, al1, al2, al3;
        ldmx4(ah0, ah1, ah2, ah3, ah_base + kt * 32);
        ldmx4(al0, al1, al2, al3, al_base + kt * 32);

        unsigned bkoff = kt * 16 * SROW * 2;
        unsigned h0, h1, h2, h3, l0, l1, l2, l3;

        ldmx4t(h0, h1, h2, h3, bh_base + bkoff);
        ldmx4t(l0, l1, l2, l3, bl_base + bkoff);
        mma16816(c[0], ah0, ah1, ah2, ah3, h0, h1);
        mma16816(c[1], ah0, ah1, ah2, ah3, h2, h3);
        mma16816(c[0], ah0, ah1, ah2, ah3, l0, l1);
        mma16816(c[1], ah0, ah1, ah2, ah3, l2, l3);
        mma16816(c[0], al0, al1, al2, al3, h0, h1);
        mma16816(c[1], al0, al1, al2, al3, h2, h3);

        ldmx4t(h0, h1, h2, h3, bh_base + bkoff + 32);
        ldmx4t(l0, l1, l2, l3, bl_base + bkoff + 32);
        mma16816(c[2], ah0, ah1, ah2, ah3, h0, h1);
        mma16816(c[3], ah0, ah1, ah2, ah3, h2, h3);
        mma16816(c[2], ah0, ah1, ah2, ah3, l0, l1);
        mma16816(c[3], ah0, ah1, ah2, ah3, l2, l3);
        mma16816(c[2], al0, al1, al2, al3, h0, h1);
        mma16816(c[3], al0, al1, al2, al3, h2, h3);
    }

    // epilogue
    int r0 = mt * 16 + (lane >> 2);
    int node0 = blockIdx.x * NPB + r0;
    int node1 = node0 + 8;
    bool v0 = node0 < NN, v1 = node1 < NN;
    float no0 = 1.0f, no1 = 1.0f;
    if (SCALE_OUT) {
        if (v0) no0 = __ldg(&g_norm_out[node0]);
        if (v1) no1 = __ldg(&g_norm_out[node1]);
    }
    #pragma unroll
    for (int j = 0; j < 4; j++) {
        int col = n0 + 8 * j + ((lane & 3) << 1);
        float d0 = c[j][0], d1 = c[j][1], d2 = c[j][2], d3 = c[j][3];
        if (RELU) {
            d0 = fmaxf(d0, 0.0f); d1 = fmaxf(d1, 0.0f);
            d2 = fmaxf(d2, 0.0f); d3 = fmaxf(d3, 0.0f);
        }
        d0 *= no0; d1 *= no0; d2 *= no1; d3 *= no1;
        if (v0) *(float2*)(xout + (size_t)node0 * HH + col) = make_float2(d0, d1);
        if (v1) *(float2*)(xout + (size_t)node1 * HH + col) = make_float2(d2, d3);
    }
}

// ---------------- final pair pooling + 2-layer MLP ----------------

__global__ void k_final(const float* __restrict__ x, const int* __restrict__ pair,
                        const float* __restrict__ l1w, const float* __restrict__ l1b,
                        const float* __restrict__ l2w, const float* __restrict__ l2b,
                        float* __restrict__ out)
{
    __shared__ float sh[HH];
    __shared__ float sred[2];
    int t = threadIdx.x;  // 64 threads
    int p0 = pair[0], p1 = pair[1];
    sh[t] = x[(size_t)p0 * HH + t] * x[(size_t)p1 * HH + t];
    __syncthreads();
    float o = l1b[t];
    #pragma unroll 8
    for (int k = 0; k < HH; k++) o += sh[k] * l1w[k * HH + t];
    o = fmaxf(o, 0.0f);
    float p = o * l2w[t];
    #pragma unroll
    for (int off = 16; off; off >>= 1) p += __shfl_down_sync(0xffffffffu, p, off);
    if ((t & 31) == 0) sred[t >> 5] = p;
    __syncthreads();
    if (t == 0) {
        out[0] = sred[0] + sred[1] + l2b[0];
        g_total = 0;    // restore counter invariant for next replay
    }
}

// ---------------- launch ----------------

extern "C" void kernel_launch(void* const* d_in, const int* in_sizes, int n_in,
                              void* d_out, int out_size)
{
    const int*   z    = (const int*)d_in[0];
    const int*   src  = (const int*)d_in[1];
    const int*   dst  = (const int*)d_in[2];
    const int*   pair = (const int*)d_in[3];
    const float* zt   = (const float*)d_in[4];
    const float* W1   = (const float*)d_in[5];
    const float* b1   = (const float*)d_in[6];
    const float* W2   = (const float*)d_in[7];
    const float* b2   = (const float*)d_in[8];
    const float* W3   = (const float*)d_in[9];
    const float* b3   = (const float*)d_in[10];
    const float* l1w  = (const float*)d_in[11];
    const float* l1b  = (const float*)d_in[12];
    const float* l2w  = (const float*)d_in[13];
    const float* l2b  = (const float*)d_in[14];
    float* out = (float*)d_out;

    float *xA = nullptr, *xB = nullptr;
    __half *Wh = nullptr, *Wl = nullptr;
    cudaGetSymbolAddress((void**)&xA, g_xA);
    cudaGetSymbolAddress((void**)&xB, g_xB);
    cudaGetSymbolAddress((void**)&Wh, g_Wh);
    cudaGetSymbolAddress((void**)&Wl, g_Wl);

    k_degrees<<<(EE + 255) / 256, 256>>>(src, dst);
    k_offsets<<<(NN + 255) / 256, 256>>>(W1, W2, W3);
    k_csrembed<<<(EE + 255) / 256, 256>>>(src, dst, z, zt);

    // launch #4 -> gets profiled (layer-1 gather)
    k_gather<<<GATB, 256>>>(xA);
    k_gemm<true,  true ><<<GBLK, 256>>>(Wh,        Wl,        b1, xB);
    k_gather<<<GATB, 256>>>(xB);
    k_gemm<true,  true ><<<GBLK, 256>>>(Wh + 4096, Wl + 4096, b2, xA);
    k_gather<<<GATB, 256>>>(xA);
    k_gemm<false, false><<<GBLK, 256>>>(Wh + 8192, Wl + 8192, b3, xB);

    k_final<<<1, 64>>>(xB, pair, l1w, l1b, l2w, l2b, out);
}

// round 15
// speedup vs baseline: 1.0781x; 1.0781x over previous
#include <cuda_runtime.h>
#include <cuda_fp16.h>

#define NN 100000
#define EE 1250000
#define HH 64
#define NPB 64                        // nodes per gemm-block
#define GBLK ((NN + NPB - 1) / NPB)   // 1563
#define SROW 72                       // smem row stride in halves (ldmatrix conflict-free)
#define NPW 2                         // nodes per gather-warp (wave-quantization fix)
#define GATB ((NN + 8 * NPW - 1) / (8 * NPW))   // 6250 gather blocks

// ---- scratch (device globals, zero-initialized at load; k_offsets re-zeros
// the degree arrays and k_final re-zeros g_total, so every replay sees zeros) ----
__device__ int   g_in_deg[NN];
__device__ int   g_out_deg[NN];
__device__ int   g_total;
__device__ float g_norm_out[NN];
__device__ float g_norm_in[NN];
__device__ int   g_row_off[NN];
__device__ int   g_cursor[NN];        // after k_csrembed: cursor[i] == row end
__device__ int   g_csr[EE];
__device__ __align__(16) __half g_hA[(size_t)NN * HH];
__device__ __align__(16) __half g_hB[(size_t)NN * HH];
__device__ __align__(16) __half g_aggh[(size_t)NN * HH];  // gather out, hi
__device__ __align__(16) __half g_aggl[(size_t)NN * HH];  // gather out, lo
__device__ __align__(16) __half g_Wh[3 * HH * HH];        // W hi, 3 layers
__device__ __align__(16) __half g_Wl[3 * HH * HH];        // W lo, 3 layers
__device__ __align__(16) float  g_bufF[(size_t)NN * HH];  // final fp32 features

__device__ __forceinline__ void split2(float v, __half& hi, __half& lo) {
    hi = __float2half_rn(v);
    lo = __float2half_rn(v - __half2float(hi));
}

// ---------------- setup kernels ----------------

__global__ void k_degrees(const int* __restrict__ src, const int* __restrict__ dst) {
    int e = blockIdx.x * blockDim.x + threadIdx.x;
    if (e < EE) {
        atomicAdd(&g_out_deg[src[e]], 1);
        atomicAdd(&g_in_deg[dst[e]], 1);
    }
}

// offsets + norms; zeros degree arrays; also splits the 3 weight matrices hi/lo
__global__ void k_offsets(const float* __restrict__ W1, const float* __restrict__ W2,
                          const float* __restrict__ W3) {
    int i = blockIdx.x * blockDim.x + threadIdx.x;
    if (i < NN) {
        int d  = g_in_deg[i];
        int od = g_out_deg[i];
        int off = atomicAdd(&g_total, d);
        g_row_off[i] = off;
        g_cursor[i]  = off;
        g_norm_in[i]  = rsqrtf(fmaxf((float)d, 1.0f));
        g_norm_out[i] = rsqrtf(fmaxf((float)od, 1.0f));
        g_in_deg[i] = 0;
        g_out_deg[i] = 0;
    }
    if (i < 3 * HH * HH) {
        int layer = i >> 12;
        int idx   = i & 4095;
        const float* Wp = (layer == 0) ? W1 : (layer == 1) ? W2 : W3;
        __half hi, lo;
        split2(__ldg(&Wp[idx]), hi, lo);
        g_Wh[i] = hi;
        g_Wl[i] = lo;
    }
}

__global__ void k_csrembed(const int* __restrict__ src, const int* __restrict__ dst,
                           const int* __restrict__ z, const float* __restrict__ zt) {
    int i = blockIdx.x * blockDim.x + threadIdx.x;
    if (i < EE) {
        int p = atomicAdd(&g_cursor[dst[i]], 1);
        g_csr[p] = src[i];
    }
    if (i < NN * 8) {
        int n  = i >> 3;
        int c8 = (i & 7) << 3;
        float no = g_norm_out[n];
        const float4* r = (const float4*)(zt + (size_t)__ldg(&z[n]) * HH + c8);
        float4 v0 = __ldg(r), v1 = __ldg(r + 1);
        __half2 h0 = __floats2half2_rn(v0.x * no, v0.y * no);
        __half2 h1 = __floats2half2_rn(v0.z * no, v0.w * no);
        __half2 h2 = __floats2half2_rn(v1.x * no, v1.y * no);
        __half2 h3 = __floats2half2_rn(v1.z * no, v1.w * no);
        uint4 pack;
        pack.x = *(unsigned*)&h0; pack.y = *(unsigned*)&h1;
        pack.z = *(unsigned*)&h2; pack.w = *(unsigned*)&h3;
        *(uint4*)(g_hA + (size_t)n * HH + c8) = pack;
    }
}

// ---------------- gather kernel ----------------
// 256 threads, 8 warps, warp = NPW(2) nodes (fine-grained: no wave quantization).
// fp16 feature rows (128B = 1 line/edge). 2 edges in flight per iteration PAIR:
// lanes 0-15 serve even edges, 16-31 odd edges; each iteration issues TWO
// independent row loads per lane (edges j+half and j+2+half) before consuming
// -> 4 outstanding LDGs/warp, double the latency hiding of one-pair-at-a-time.
// Accumulation order per lane-half is unchanged (bit-identical results).

__global__ void __launch_bounds__(256, 8) k_gather(const __half* __restrict__ xin)
{
    int t = threadIdx.x;
    int warp = t >> 5;
    int lane = t & 31;
    int half_ = lane >> 4;
    int fl    = lane & 15;
    int gw = blockIdx.x * 8 + warp;   // global warp id

    #pragma unroll 1
    for (int nl = 0; nl < NPW; nl++) {
        int n = gw * NPW + nl;
        if (n >= NN) break;

        int beg = g_row_off[n];
        int end = g_cursor[n];
        float4 acc = make_float4(0.0f, 0.0f, 0.0f, 0.0f);

        for (int base = beg; base < end; base += 32) {
            int cnt = min(32, end - base);
            int idx = (lane < cnt) ? __ldg(&g_csr[base + lane]) : 0;
            int ioff = idx << 7;          // byte offset of 128B fp16 row
            #pragma unroll 2
            for (int j = 0; j < cnt; j += 4) {
                int e0 = j + half_;
                int e1 = j + 2 + half_;
                int o0 = __shfl_sync(0xffffffffu, ioff, e0);
                int o1 = __shfl_sync(0xffffffffu, ioff, e1);
                bool b0 = e0 < cnt, b1 = e1 < cnt;
                uint2 v0 = make_uint2(0u, 0u), v1 = make_uint2(0u, 0u);
                if (b0) v0 = __ldg((const uint2*)((const char*)xin + o0) + fl);
                if (b1) v1 = __ldg((const uint2*)((const char*)xin + o1) + fl);
                if (b0) {
                    float2 f0 = __half22float2(*(__half2*)&v0.x);
                    float2 f1 = __half22float2(*(__half2*)&v0.y);
                    acc.x += f0.x; acc.y += f0.y;
                    acc.z += f1.x; acc.w += f1.y;
                }
                if (b1) {
                    float2 f0 = __half22float2(*(__half2*)&v1.x);
                    float2 f1 = __half22float2(*(__half2*)&v1.y);
                    acc.x += f0.x; acc.y += f0.y;
                    acc.z += f1.x; acc.w += f1.y;
                }
            }
        }

        acc.x += __shfl_xor_sync(0xffffffffu, acc.x, 16);
        acc.y += __shfl_xor_sync(0xffffffffu, acc.y, 16);
        acc.z += __shfl_xor_sync(0xffffffffu, acc.z, 16);
        acc.w += __shfl_xor_sync(0xffffffffu, acc.w, 16);

        if (half_ == 0) {
            float ni = g_norm_in[n];
            float vv[4] = {acc.x * ni, acc.y * ni, acc.z * ni, acc.w * ni};
            __half hi[4], lo[4];
            #pragma unroll
            for (int k = 0; k < 4; k++) split2(vv[k], hi[k], lo[k]);
            *(uint2*)(g_aggh + (size_t)n * HH + (fl << 2)) = *(uint2*)hi;
            *(uint2*)(g_aggl + (size_t)n * HH + (fl << 2)) = *(uint2*)lo;
        }
    }
}

// ---------------- mma helpers ----------------

__device__ __forceinline__ unsigned su32(const void* p) {
    return (unsigned)__cvta_generic_to_shared(p);
}
__device__ __forceinline__ void ldmx4(unsigned& r0, unsigned& r1, unsigned& r2,
                                      unsigned& r3, unsigned addr) {
    asm volatile("ldmatrix.sync.aligned.m8n8.x4.shared.b16 {%0,%1,%2,%3}, [%4];"
                 : "=r"(r0), "=r"(r1), "=r"(r2), "=r"(r3) : "r"(addr));
}
__device__ __forceinline__ void ldmx4t(unsigned& r0, unsigned& r1, unsigned& r2,
                                       unsigned& r3, unsigned addr) {
    asm volatile("ldmatrix.sync.aligned.m8n8.x4.trans.shared.b16 {%0,%1,%2,%3}, [%4];"
                 : "=r"(r0), "=r"(r1), "=r"(r2), "=r"(r3) : "r"(addr));
}
__device__ __forceinline__ void mma16816(float* c, unsigned a0, unsigned a1,
                                         unsigned a2, unsigned a3,
                                         unsigned b0, unsigned b1) {
    asm volatile(
        "mma.sync.aligned.m16n8k16.row.col.f32.f16.f16.f32 "
        "{%0,%1,%2,%3}, {%4,%5,%6,%7}, {%8,%9}, {%0,%1,%2,%3};"
        : "+f"(c[0]), "+f"(c[1]), "+f"(c[2]), "+f"(c[3])
        : "r"(a0), "r"(a1), "r"(a2), "r"(a3), "r"(b0), "r"(b1));
}

// ---------------- GEMM kernel (tensor cores, double-fp16, copy staging) ----------------
// 256 threads, 64 nodes/block, static smem 37KB, 4 blocks/SM.
// Staging = pure uint4 copies (hi/lo precomputed). D = Ah*Wh + Ah*Wl + Al*Wh.
// warp w (0..7): m-tile (w&3) x n-half (w>>2).

template <bool OUT_HALF, bool RELU, bool SCALE_OUT>
__global__ void __launch_bounds__(256, 4) k_gemm(
    const __half* __restrict__ Wh, const __half* __restrict__ Wl,
    const float* __restrict__ b,
    void* __restrict__ xout_v)
{
    __shared__ __half sW_hi[HH * SROW];
    __shared__ __half sW_lo[HH * SROW];
    __shared__ __half sa_hi[NPB * SROW];
    __shared__ __half sa_lo[NPB * SROW];
    __shared__ float  sb[HH];

    int t = threadIdx.x;

    // W stage: 512 uint4 chunks each (pure copies)
    #pragma unroll
    for (int c = 0; c < 2; c++) {
        int idx = t + c * 256;               // 0..511
        int row = idx >> 3, c8 = (idx & 7) << 3;
        *(uint4*)(sW_hi + row * SROW + c8) = __ldg((const uint4*)Wh + idx);
        *(uint4*)(sW_lo + row * SROW + c8) = __ldg((const uint4*)Wl + idx);
    }
    // agg stage: 512 uint4 chunks each
    #pragma unroll
    for (int c = 0; c < 2; c++) {
        int idx = t + c * 256;
        int row = idx >> 3, c8 = (idx & 7) << 3;
        int node = blockIdx.x * NPB + row;
        uint4 vh = make_uint4(0, 0, 0, 0), vl = make_uint4(0, 0, 0, 0);
        if (node < NN) {
            vh = __ldg((const uint4*)(g_aggh + (size_t)node * HH + c8));
            vl = __ldg((const uint4*)(g_aggl + (size_t)node * HH + c8));
        }
        *(uint4*)(sa_hi + row * SROW + c8) = vh;
        *(uint4*)(sa_lo + row * SROW + c8) = vl;
    }
    if (t < HH) sb[t] = b[t];
    __syncthreads();

    int warp = t >> 5;
    int lane = t & 31;
    int mt = warp & 3;           // m-tile: rows mt*16..+15
    int n0 = (warp >> 2) << 5;   // n-half: cols n0..n0+31

    float c[4][4];
    #pragma unroll
    for (int j = 0; j < 4; j++) {
        int col = n0 + 8 * j + ((lane & 3) << 1);
        float b0v = sb[col], b1v = sb[col + 1];
        c[j][0] = b0v; c[j][1] = b1v; c[j][2] = b0v; c[j][3] = b1v;
    }

    int rIn = (lane & 7) + ((lane >> 3) & 1) * 8;
    int cIn = (lane >> 4) * 8;
    unsigned aoff = ((mt * 16 + rIn) * SROW + cIn) * 2;
    unsigned boff = (rIn * SROW + n0 + cIn) * 2;
    unsigned ah_base = su32(sa_hi) + aoff;
    unsigned al_base = su32(sa_lo) + aoff;
    unsigned bh_base = su32(sW_hi) + boff;
    unsigned bl_base = su32(sW_lo) + boff;

    #pragma unroll
    for (int kt = 0; kt < 4; kt++) {
        unsigned ah0, ah1, ah2, ah3, al0, al1, al2, al3;
        ldmx4(ah0, ah1, ah2, ah3, ah_base + kt * 32);
        ldmx4(al0, al1, al2, al3, al_base + kt * 32);

        unsigned bkoff = kt * 16 * SROW * 2;
        unsigned h0, h1, h2, h3, l0, l1, l2, l3;

        ldmx4t(h0, h1, h2, h3, bh_base + bkoff);
        ldmx4t(l0, l1, l2, l3, bl_base + bkoff);
        mma16816(c[0], ah0, ah1, ah2, ah3, h0, h1);
        mma16816(c[1], ah0, ah1, ah2, ah3, h2, h3);
        mma16816(c[0], ah0, ah1, ah2, ah3, l0, l1);
        mma16816(c[1], ah0, ah1, ah2, ah3, l2, l3);
        mma16816(c[0], al0, al1, al2, al3, h0, h1);
        mma16816(c[1], al0, al1, al2, al3, h2, h3);

        ldmx4t(h0, h1, h2, h3, bh_base + bkoff + 32);
        ldmx4t(l0, l1, l2, l3, bl_base + bkoff + 32);
        mma16816(c[2], ah0, ah1, ah2, ah3, h0, h1);
        mma16816(c[3], ah0, ah1, ah2, ah3, h2, h3);
        mma16816(c[2], ah0, ah1, ah2, ah3, l0, l1);
        mma16816(c[3], ah0, ah1, ah2, ah3, l2, l3);
        mma16816(c[2], al0, al1, al2, al3, h0, h1);
        mma16816(c[3], al0, al1, al2, al3, h2, h3);
    }

    // epilogue
    int r0 = mt * 16 + (lane >> 2);
    int node0 = blockIdx.x * NPB + r0;
    int node1 = node0 + 8;
    bool v0 = node0 < NN, v1 = node1 < NN;
    float no0 = 1.0f, no1 = 1.0f;
    if (SCALE_OUT) {
        if (v0) no0 = __ldg(&g_norm_out[node0]);
        if (v1) no1 = __ldg(&g_norm_out[node1]);
    }
    #pragma unroll
    for (int j = 0; j < 4; j++) {
        int col = n0 + 8 * j + ((lane & 3) << 1);
        float d0 = c[j][0], d1 = c[j][1], d2 = c[j][2], d3 = c[j][3];
        if (RELU) {
            d0 = fmaxf(d0, 0.0f); d1 = fmaxf(d1, 0.0f);
            d2 = fmaxf(d2, 0.0f); d3 = fmaxf(d3, 0.0f);
        }
        d0 *= no0; d1 *= no0; d2 *= no1; d3 *= no1;
        if (OUT_HALF) {
            __half* o = (__half*)xout_v;
            if (v0) { __half2 h = __floats2half2_rn(d0, d1);
                      *(unsigned*)(o + (size_t)node0 * HH + col) = *(unsigned*)&h; }
            if (v1) { __half2 h = __floats2half2_rn(d2, d3);
                      *(unsigned*)(o + (size_t)node1 * HH + col) = *(unsigned*)&h; }
        } else {
            float* o = (float*)xout_v;
            if (v0) *(float2*)(o + (size_t)node0 * HH + col) = make_float2(d0, d1);
            if (v1) *(float2*)(o + (size_t)node1 * HH + col) = make_float2(d2, d3);
        }
    }
}

// ---------------- final pair pooling + 2-layer MLP ----------------

__global__ void k_final(const float* __restrict__ x, const int* __restrict__ pair,
                        const float* __restrict__ l1w, const float* __restrict__ l1b,
                        const float* __restrict__ l2w, const float* __restrict__ l2b,
                        float* __restrict__ out)
{
    __shared__ float sh[HH];
    __shared__ float sred[2];
    int t = threadIdx.x;  // 64 threads
    int p0 = pair[0], p1 = pair[1];
    sh[t] = x[(size_t)p0 * HH + t] * x[(size_t)p1 * HH + t];
    __syncthreads();
    float o = l1b[t];
    #pragma unroll 8
    for (int k = 0; k < HH; k++) o += sh[k] * l1w[k * HH + t];
    o = fmaxf(o, 0.0f);
    float p = o * l2w[t];
    #pragma unroll
    for (int off = 16; off; off >>= 1) p += __shfl_down_sync(0xffffffffu, p, off);
    if ((t & 31) == 0) sred[t >> 5] = p;
    __syncthreads();
    if (t == 0) {
        out[0] = sred[0] + sred[1] + l2b[0];
        g_total = 0;    // restore counter invariant for next replay
    }
}

// ---------------- launch ----------------

extern "C" void kernel_launch(void* const* d_in, const int* in_sizes, int n_in,
                              void* d_out, int out_size)
{
    const int*   z    = (const int*)d_in[0];
    const int*   src  = (const int*)d_in[1];
    const int*   dst  = (const int*)d_in[2];
    const int*   pair = (const int*)d_in[3];
    const float* zt   = (const float*)d_in[4];
    const float* W1   = (const float*)d_in[5];
    const float* b1   = (const float*)d_in[6];
    const float* W2   = (const float*)d_in[7];
    const float* b2   = (const float*)d_in[8];
    const float* W3   = (const float*)d_in[9];
    const float* b3   = (const float*)d_in[10];
    const float* l1w  = (const float*)d_in[11];
    const float* l1b  = (const float*)d_in[12];
    const float* l2w  = (const float*)d_in[13];
    const float* l2b  = (const float*)d_in[14];
    float* out = (float*)d_out;

    __half *hA = nullptr, *hB = nullptr, *Wh = nullptr, *Wl = nullptr;
    float *bufF = nullptr;
    cudaGetSymbolAddress((void**)&hA, g_hA);
    cudaGetSymbolAddress((void**)&hB, g_hB);
    cudaGetSymbolAddress((void**)&Wh, g_Wh);
    cudaGetSymbolAddress((void**)&Wl, g_Wl);
    cudaGetSymbolAddress((void**)&bufF, g_bufF);

    k_degrees<<<(EE + 255) / 256, 256>>>(src, dst);
    k_offsets<<<(NN + 255) / 256, 256>>>(W1, W2, W3);
    k_csrembed<<<(EE + 255) / 256, 256>>>(src, dst, z, zt);

    // launch #4 -> gets profiled (layer-1 gather)
    k_gather<<<GATB, 256>>>(hA);
    k_gemm<true,  true,  true ><<<GBLK, 256>>>(Wh,        Wl,        b1, hB);
    k_gather<<<GATB, 256>>>(hB);
    k_gemm<true,  true,  true ><<<GBLK, 256>>>(Wh + 4096, Wl + 4096, b2, hA);
    k_gather<<<GATB, 256>>>(hA);
    k_gemm<false, false, false><<<GBLK, 256>>>(Wh + 8192, Wl + 8192, b3, bufF);

    k_final<<<1, 64>>>(bufF, pair, l1w, l1b, l2w, l2b, out);
}